// round 8
// baseline (speedup 1.0000x reference)
#include <cuda_runtime.h>
#include <cstdint>
#include <mma.h>

using namespace nvcuda;

static constexpr int NP   = 100000;     // points
static constexpr int NPAD = 100096;     // multiple of 128 (782 * 128)
static constexpr int CH   = 128;
static constexpr int HH   = 64;

// Scratch (device globals; no allocations allowed)
__device__ float g_y [(size_t)NPAD * CH];   // y = x@w1 + b1
__device__ float g_r1[(size_t)NPAD * HH];   // relu(sconv1)
__device__ float g_r2[(size_t)NPAD * HH];   // relu(sconv2)

// ---------------------------------------------------------------------------
// helpers
// ---------------------------------------------------------------------------
__device__ __forceinline__ unsigned smem_u32(const void* p) {
    return (unsigned)__cvta_generic_to_shared(p);
}
__device__ __forceinline__ void cp16(unsigned dst, const void* src, int src_size) {
    asm volatile("cp.async.cg.shared.global [%0], [%1], 16, %2;"
                 :: "r"(dst), "l"(src), "r"(src_size));
}
__device__ __forceinline__ void cp_commit() { asm volatile("cp.async.commit_group;"); }
template <int N>
__device__ __forceinline__ void cp_wait() {
    asm volatile("cp.async.wait_group %0;" :: "n"(N));
}

// ---------------------------------------------------------------------------
// GEMM1: g_y[n,:] = x[n,:] @ w1 + b1      (verbatim R2-proven)
// ---------------------------------------------------------------------------
__global__ __launch_bounds__(256) void gemm1_kernel(
    const float* __restrict__ x,
    const float* __restrict__ w1,
    const float* __restrict__ b1)
{
    extern __shared__ float smem[];
    float* As = smem;               // 64 x 132
    float* Bs = smem + 64 * 132;    // 128 x 132

    const int tid = threadIdx.x;
    const int rowBase = blockIdx.x * 64;

    #pragma unroll
    for (int i = 0; i < 8; i++) {
        int j = tid + i * 256;
        int row = j >> 5, seg = j & 31;
        int n = rowBase + row;
        cp16(smem_u32(As + row * 132 + seg * 4), x + (size_t)n * 128 + seg * 4,
             (n < NP) ? 16 : 0);
    }
    #pragma unroll
    for (int i = 0; i < 16; i++) {
        int j = tid + i * 256;
        int row = j >> 5, seg = j & 31;
        cp16(smem_u32(Bs + row * 132 + seg * 4), w1 + j * 4, 16);
    }
    cp_commit();
    cp_wait<0>();
    __syncthreads();

    const int warp = tid >> 5;
    const int mw = warp >> 1, nw = warp & 1;

    wmma::fragment<wmma::accumulator, 16, 16, 8, float> c[4];
    #pragma unroll
    for (int f = 0; f < 4; f++) wmma::fill_fragment(c[f], 0.f);

    #pragma unroll
    for (int kk = 0; kk < 16; kk++) {
        wmma::fragment<wmma::matrix_a, 16, 16, 8, wmma::precision::tf32, wmma::row_major> a;
        wmma::load_matrix_sync(a, As + (mw * 16) * 132 + kk * 8, 132);
        #pragma unroll
        for (int f = 0; f < 4; f++) {
            wmma::fragment<wmma::matrix_b, 16, 16, 8, wmma::precision::tf32, wmma::row_major> b;
            wmma::load_matrix_sync(b, Bs + (kk * 8) * 132 + nw * 64 + f * 16, 132);
            wmma::mma_sync(c[f], a, b, c[f]);
        }
    }
    __syncthreads();
    #pragma unroll
    for (int f = 0; f < 4; f++)
        wmma::store_matrix_sync(As + (mw * 16) * 132 + nw * 64 + f * 16, c[f], 132,
                                wmma::mem_row_major);
    __syncthreads();

    #pragma unroll
    for (int i = 0; i < 8; i++) {
        int j = tid + i * 256;
        int row = j >> 5, seg = j & 31;
        int n = rowBase + row;
        float4 v  = *(float4*)(As + row * 132 + seg * 4);
        float4 bb = *(const float4*)(b1 + seg * 4);
        v.x += bb.x; v.y += bb.y; v.z += bb.z; v.w += bb.w;
        *(float4*)(g_y + (size_t)n * 128 + seg * 4) = v;
    }
}

// ---------------------------------------------------------------------------
// sconv (R2-proven wmma math core; structural changes only):
//   out[n,0:64] = relu( sum_k feat[nbr[k,n]] @ rw[k] + rb )
// CTA: 128 rows x 64 cols, 256 thr (8 warps), warp tile 16 rows x 64 cols,
// 4 persistent accumulator fragments per warp across all 27 offsets.
// Double-buffered cp.async A/B; neighbor indices prefetched 2 stages ahead
// into registers. smem = (2*128 + 2*64)*68 floats = 104448 B; 2 CTAs/SM.
// ---------------------------------------------------------------------------
template <int SRC>
__global__ __launch_bounds__(256, 2) void sconv_wmma(
    const int*   __restrict__ nbr,
    const float* __restrict__ rw,
    const float* __restrict__ rb)
{
    extern __shared__ float sm[];
    // A(buf): sm + buf*8704          (128 rows x 68 floats)
    // B(buf): sm + 17408 + buf*4352  ( 64 rows x 68 floats)

    const float* feat = (SRC == 0) ? g_y : g_r1;
    float*       outp = (SRC == 0) ? g_r1 : g_r2;
    const int    ldf  = (SRC == 0) ? 128 : 64;

    const int tid  = threadIdx.x;
    const int warp = tid >> 5;           // 0..7 -> rows 16*warp
    const int rowBase = blockIdx.x * 128;

    const int arow  = tid >> 1;          // 0..127
    const int ahalf = tid & 1;           // halves (32 floats)
    const int brow  = tid >> 2;          // 0..63 (B row = c)
    const int bq    = tid & 3;           // quarter (16 floats)
    const int an    = rowBase + arow;

    auto ldIdx = [&](int kk) -> int {
        return (an < NP) ? __ldg(nbr + (size_t)kk * NP + an) : -1;
    };
    auto fillA = [&](int buf, int idx) {
        int sz = (idx >= 0) ? 16 : 0;
        const float* src = feat + (size_t)(idx < 0 ? 0 : idx) * ldf + ahalf * 32;
        unsigned d = smem_u32(sm + buf * 8704 + arow * 68 + ahalf * 32);
        #pragma unroll
        for (int s = 0; s < 8; s++)
            cp16(d + (unsigned)(s * 16), src + s * 4, sz);
    };
    auto fillB = [&](int kk, int buf) {
        const float* src = rw + (size_t)kk * 4096 + brow * 64 + bq * 16;
        unsigned d = smem_u32(sm + 17408 + buf * 4352 + brow * 68 + bq * 16);
        #pragma unroll
        for (int s = 0; s < 4; s++)
            cp16(d + (unsigned)(s * 16), src + s * 4, 16);
    };

    wmma::fragment<wmma::accumulator, 16, 16, 8, float> c[4];
    #pragma unroll
    for (int f = 0; f < 4; f++) wmma::fill_fragment(c[f], 0.f);

    int idxNxt = ldIdx(0);
    fillA(0, idxNxt);
    fillB(0, 0);
    cp_commit();
    idxNxt = ldIdx(1);

    for (int kk = 0; kk < 27; kk++) {
        const int buf = kk & 1;
        if (kk + 1 < 27) {
            fillA(buf ^ 1, idxNxt);
            fillB(kk + 1, buf ^ 1);
            cp_commit();
            if (kk + 2 < 27) idxNxt = ldIdx(kk + 2);  // hidden under MMA below
            cp_wait<1>();                 // stage kk landed (this thread)
        } else {
            cp_wait<0>();
        }
        __syncthreads();                  // stage kk visible CTA-wide

        const float* Ab = sm + buf * 8704 + (warp * 16) * 68;
        const float* Bb = sm + 17408 + buf * 4352;

        #pragma unroll
        for (int k8 = 0; k8 < 8; k8++) {
            wmma::fragment<wmma::matrix_a, 16, 16, 8, wmma::precision::tf32, wmma::row_major> a;
            wmma::load_matrix_sync(a, Ab + k8 * 8, 68);
            #pragma unroll
            for (int f = 0; f < 4; f++) {
                wmma::fragment<wmma::matrix_b, 16, 16, 8, wmma::precision::tf32, wmma::row_major> b;
                wmma::load_matrix_sync(b, Bb + (k8 * 8) * 68 + f * 16, 68);
                wmma::mma_sync(c[f], a, b, c[f]);
            }
        }
        __syncthreads();                  // all warps done reading buf
    }

    // epilogue: stage into A-buf0 region, bias + relu, write out
    #pragma unroll
    for (int f = 0; f < 4; f++)
        wmma::store_matrix_sync(sm + (warp * 16) * 68 + f * 16, c[f], 68,
                                wmma::mem_row_major);
    __syncthreads();

    #pragma unroll
    for (int i = 0; i < 8; i++) {
        int j = tid + i * 256;            // 0..2047 -> 128 rows x 16 float4
        int row = j >> 4, seg = j & 15;
        float4 v  = *(float4*)(sm + row * 68 + seg * 4);
        float4 bb = *(const float4*)(rb + seg * 4);
        v.x = fmaxf(v.x + bb.x, 0.f);
        v.y = fmaxf(v.y + bb.y, 0.f);
        v.z = fmaxf(v.z + bb.z, 0.f);
        v.w = fmaxf(v.w + bb.w, 0.f);
        *(float4*)(outp + (size_t)(rowBase + row) * 64 + seg * 4) = v;
    }
}

// ---------------------------------------------------------------------------
// GEMM2: out = x + concat(r2 + 2*y[:,:64], y[:,64:]) @ w2 + b2   (verbatim R2)
// ---------------------------------------------------------------------------
__global__ __launch_bounds__(256) void gemm2_kernel(
    const float* __restrict__ x,
    const float* __restrict__ w2,
    const float* __restrict__ b2,
    float* __restrict__ out)
{
    extern __shared__ float smem[];
    float* As = smem;
    float* Bs = smem + 64 * 132;

    const int tid = threadIdx.x;
    const int rowBase = blockIdx.x * 64;

    #pragma unroll
    for (int i = 0; i < 16; i++) {
        int j = tid + i * 256;
        int row = j >> 5, seg = j & 31;
        cp16(smem_u32(Bs + row * 132 + seg * 4), w2 + j * 4, 16);
    }
    cp_commit();

    #pragma unroll
    for (int i = 0; i < 8; i++) {
        int j = tid + i * 256;
        int row = j >> 5, seg = j & 31;
        int n = rowBase + row;
        float4 v;
        if (seg < 16) {
            float4 r = *(const float4*)(g_r2 + (size_t)n * 64  + seg * 4);
            float4 y = *(const float4*)(g_y  + (size_t)n * 128 + seg * 4);
            v.x = fmaf(2.f, y.x, r.x);
            v.y = fmaf(2.f, y.y, r.y);
            v.z = fmaf(2.f, y.z, r.z);
            v.w = fmaf(2.f, y.w, r.w);
        } else {
            v = *(const float4*)(g_y + (size_t)n * 128 + seg * 4);
        }
        *(float4*)(As + row * 132 + seg * 4) = v;
    }
    cp_wait<0>();
    __syncthreads();

    const int warp = tid >> 5;
    const int mw = warp >> 1, nw = warp & 1;

    wmma::fragment<wmma::accumulator, 16, 16, 8, float> c[4];
    #pragma unroll
    for (int f = 0; f < 4; f++) wmma::fill_fragment(c[f], 0.f);

    #pragma unroll
    for (int kk = 0; kk < 16; kk++) {
        wmma::fragment<wmma::matrix_a, 16, 16, 8, wmma::precision::tf32, wmma::row_major> a;
        wmma::load_matrix_sync(a, As + (mw * 16) * 132 + kk * 8, 132);
        #pragma unroll
        for (int f = 0; f < 4; f++) {
            wmma::fragment<wmma::matrix_b, 16, 16, 8, wmma::precision::tf32, wmma::row_major> b;
            wmma::load_matrix_sync(b, Bs + (kk * 8) * 132 + nw * 64 + f * 16, 132);
            wmma::mma_sync(c[f], a, b, c[f]);
        }
    }
    __syncthreads();
    #pragma unroll
    for (int f = 0; f < 4; f++)
        wmma::store_matrix_sync(As + (mw * 16) * 132 + nw * 64 + f * 16, c[f], 132,
                                wmma::mem_row_major);
    __syncthreads();

    #pragma unroll
    for (int i = 0; i < 8; i++) {
        int j = tid + i * 256;
        int row = j >> 5, seg = j & 31;
        int n = rowBase + row;
        if (n < NP) {
            float4 v  = *(float4*)(As + row * 132 + seg * 4);
            float4 bb = *(const float4*)(b2 + seg * 4);
            float4 xr = *(const float4*)(x + (size_t)n * 128 + seg * 4);
            v.x += bb.x + xr.x;
            v.y += bb.y + xr.y;
            v.z += bb.z + xr.z;
            v.w += bb.w + xr.w;
            *(float4*)(out + (size_t)n * 128 + seg * 4) = v;
        }
    }
}

// ---------------------------------------------------------------------------
extern "C" void kernel_launch(void* const* d_in, const int* in_sizes, int n_in,
                              void* d_out, int out_size)
{
    const float* x   = (const float*)d_in[0];
    const float* w1  = (const float*)d_in[1];
    const float* b1  = (const float*)d_in[2];
    const float* w2  = (const float*)d_in[3];
    const float* b2  = (const float*)d_in[4];
    const float* rw1 = (const float*)d_in[5];
    const float* rb1 = (const float*)d_in[6];
    const float* rw2 = (const float*)d_in[7];
    const float* rb2 = (const float*)d_in[8];
    const int*   nbr = (const int*)  d_in[9];
    float* out = (float*)d_out;

    const int SMEM_G = (64 + 128) * 132 * (int)sizeof(float);          // ~99 KB
    const int SMEM_S = (2 * 128 + 2 * 64) * 68 * (int)sizeof(float);   // 104448 B
    static bool attr_done = false;
    if (!attr_done) {
        cudaFuncSetAttribute(gemm1_kernel,  cudaFuncAttributeMaxDynamicSharedMemorySize, SMEM_G);
        cudaFuncSetAttribute(gemm2_kernel,  cudaFuncAttributeMaxDynamicSharedMemorySize, SMEM_G);
        cudaFuncSetAttribute(sconv_wmma<0>, cudaFuncAttributeMaxDynamicSharedMemorySize, SMEM_S);
        cudaFuncSetAttribute(sconv_wmma<1>, cudaFuncAttributeMaxDynamicSharedMemorySize, SMEM_S);
        attr_done = true;
    }

    const int gridG = NPAD / 64;    // 1564
    const int gridS = NPAD / 128;   // 782

    gemm1_kernel<<<gridG, 256, SMEM_G>>>(x, w1, b1);
    sconv_wmma<0><<<gridS, 256, SMEM_S>>>(nbr, rw1, rb1);
    sconv_wmma<1><<<gridS, 256, SMEM_S>>>(nbr, rw2, rb2);
    gemm2_kernel<<<gridG, 256, SMEM_G>>>(x, w2, b2, out);
}

// round 9
// speedup vs baseline: 1.6629x; 1.6629x over previous
#include <cuda_runtime.h>
#include <cstdint>
#include <mma.h>

using namespace nvcuda;

static constexpr int NP   = 100000;     // points
static constexpr int NPAD = 100096;     // multiple of 128 (782 * 128)
static constexpr int CH   = 128;
static constexpr int HH   = 64;

// Scratch (device globals; referenced ONLY inside device code)
__device__ float g_y [(size_t)NPAD * CH];   // y = x@w1 + b1
__device__ float g_r1[(size_t)NPAD * HH];   // relu(sconv1)
__device__ float g_r2[(size_t)NPAD * HH];   // relu(sconv2)

// ---------------------------------------------------------------------------
// helpers
// ---------------------------------------------------------------------------
__device__ __forceinline__ unsigned smem_u32(const void* p) {
    return (unsigned)__cvta_generic_to_shared(p);
}
__device__ __forceinline__ void cp16(unsigned dst, const void* src, int src_size) {
    asm volatile("cp.async.cg.shared.global [%0], [%1], 16, %2;"
                 :: "r"(dst), "l"(src), "r"(src_size));
}
__device__ __forceinline__ void cp_commit() { asm volatile("cp.async.commit_group;"); }
template <int N>
__device__ __forceinline__ void cp_wait() {
    asm volatile("cp.async.wait_group %0;" :: "n"(N));
}
__device__ __forceinline__ void mma_tf32(float* d, const uint32_t* a, const uint32_t* b) {
    asm volatile(
        "mma.sync.aligned.m16n8k8.row.col.f32.tf32.tf32.f32 "
        "{%0,%1,%2,%3}, {%4,%5,%6,%7}, {%8,%9}, {%0,%1,%2,%3};"
        : "+f"(d[0]), "+f"(d[1]), "+f"(d[2]), "+f"(d[3])
        : "r"(a[0]), "r"(a[1]), "r"(a[2]), "r"(a[3]), "r"(b[0]), "r"(b[1]));
}

// ---------------------------------------------------------------------------
// GEMM1: g_y[n,:] = x[n,:] @ w1 + b1      (R2/R8-proven, unchanged)
// ---------------------------------------------------------------------------
__global__ __launch_bounds__(256) void gemm1_kernel(
    const float* __restrict__ x,
    const float* __restrict__ w1,
    const float* __restrict__ b1)
{
    extern __shared__ float smem[];
    float* As = smem;               // 64 x 132
    float* Bs = smem + 64 * 132;    // 128 x 132

    const int tid = threadIdx.x;
    const int rowBase = blockIdx.x * 64;

    #pragma unroll
    for (int i = 0; i < 8; i++) {
        int j = tid + i * 256;
        int row = j >> 5, seg = j & 31;
        int n = rowBase + row;
        cp16(smem_u32(As + row * 132 + seg * 4), x + (size_t)n * 128 + seg * 4,
             (n < NP) ? 16 : 0);
    }
    #pragma unroll
    for (int i = 0; i < 16; i++) {
        int j = tid + i * 256;
        int row = j >> 5, seg = j & 31;
        cp16(smem_u32(Bs + row * 132 + seg * 4), w1 + j * 4, 16);
    }
    cp_commit();
    cp_wait<0>();
    __syncthreads();

    const int warp = tid >> 5;
    const int mw = warp >> 1, nw = warp & 1;

    wmma::fragment<wmma::accumulator, 16, 16, 8, float> c[4];
    #pragma unroll
    for (int f = 0; f < 4; f++) wmma::fill_fragment(c[f], 0.f);

    #pragma unroll
    for (int kk = 0; kk < 16; kk++) {
        wmma::fragment<wmma::matrix_a, 16, 16, 8, wmma::precision::tf32, wmma::row_major> a;
        wmma::load_matrix_sync(a, As + (mw * 16) * 132 + kk * 8, 132);
        #pragma unroll
        for (int f = 0; f < 4; f++) {
            wmma::fragment<wmma::matrix_b, 16, 16, 8, wmma::precision::tf32, wmma::row_major> b;
            wmma::load_matrix_sync(b, Bs + (kk * 8) * 132 + nw * 64 + f * 16, 132);
            wmma::mma_sync(c[f], a, b, c[f]);
        }
    }
    __syncthreads();
    #pragma unroll
    for (int f = 0; f < 4; f++)
        wmma::store_matrix_sync(As + (mw * 16) * 132 + nw * 64 + f * 16, c[f], 132,
                                wmma::mem_row_major);
    __syncthreads();

    #pragma unroll
    for (int i = 0; i < 8; i++) {
        int j = tid + i * 256;
        int row = j >> 5, seg = j & 31;
        int n = rowBase + row;
        float4 v  = *(float4*)(As + row * 132 + seg * 4);
        float4 bb = *(const float4*)(b1 + seg * 4);
        v.x += bb.x; v.y += bb.y; v.z += bb.z; v.w += bb.w;
        *(float4*)(g_y + (size_t)n * 128 + seg * 4) = v;
    }
}

// ---------------------------------------------------------------------------
// sconv (raw mma.sync m16n8k8 tf32; weights read directly from input ptr):
//   out[n,0:64] = relu( sum_k feat[nbr[k,n]] @ rw[k] + rb )
// CTA: 128 rows x 64 cols, 8 warps (4x2), warp tile 32x32.
// Accumulators persist in registers across all 27 offsets.
// A smem: stride 68 floats (read bank = 4*lr+la3+8k8 mod 32 -> conflict-free).
// B smem: stride 72 floats (read bank = 8*la3+lr+8nt mod 32 -> conflict-free).
// B stored [c][d] direct from rw[k][c][d]; mma B col-major: b0=B[k=la3][n],
// b1=B[k=la3+4][n]  (PTX m16n8k8 fragment spec).
// Neighbor indices prefetched 2 stages ahead into registers.
// smem floats: A[2][128][68] @0, B[2][64][72] @17408; 106496 B -> 2 CTAs/SM.
// ---------------------------------------------------------------------------
template <int SRC>
__global__ __launch_bounds__(256, 2) void sconv_mma(
    const int*   __restrict__ nbr,
    const float* __restrict__ rw,
    const float* __restrict__ rb)
{
    extern __shared__ float sm[];

    const float* feat = (SRC == 0) ? g_y : g_r1;
    float*       outp = (SRC == 0) ? g_r1 : g_r2;
    const int    ldf  = (SRC == 0) ? 128 : 64;

    const int tid  = threadIdx.x;
    const int lane = tid & 31;
    const int warp = tid >> 5;
    const int wrow = warp >> 1;          // 0..3 -> rows 32*wrow
    const int wcol = warp & 1;           // 0..1 -> cols 32*wcol
    const int lr   = lane >> 2;          // 0..7
    const int la3  = lane & 3;           // 0..3
    const int rowBase = blockIdx.x * 128;

    // fill assignments
    const int arow  = tid >> 1;          // 0..127
    const int ahalf = tid & 1;           // halves (32 floats)
    const int brow  = tid >> 2;          // 0..63 (B row = c)
    const int bq    = tid & 3;           // quarter (16 floats)
    const int an    = rowBase + arow;

    auto ldIdx = [&](int kk) -> int {
        return (an < NP) ? __ldg(nbr + (size_t)kk * NP + an) : -1;
    };
    auto fillA = [&](int buf, int idx) {
        int sz = (idx >= 0) ? 16 : 0;
        const float* src = feat + (size_t)(idx < 0 ? 0 : idx) * ldf + ahalf * 32;
        unsigned d = smem_u32(sm + buf * 8704 + arow * 68 + ahalf * 32);
        #pragma unroll
        for (int s = 0; s < 8; s++)
            cp16(d + (unsigned)(s * 16), src + s * 4, sz);
    };
    auto fillB = [&](int kk, int buf) {
        const float* src = rw + (size_t)kk * 4096 + brow * 64 + bq * 16;
        unsigned d = smem_u32(sm + 17408 + buf * 4608 + brow * 72 + bq * 16);
        #pragma unroll
        for (int s = 0; s < 4; s++)
            cp16(d + (unsigned)(s * 16), src + s * 4, 16);
    };

    // accumulators: [mt][nt][4]
    float acc[2][4][4];
    #pragma unroll
    for (int mt = 0; mt < 2; mt++)
        #pragma unroll
        for (int nt = 0; nt < 4; nt++)
            #pragma unroll
            for (int q = 0; q < 4; q++) acc[mt][nt][q] = 0.f;

    // A rows this thread touches: wrow*32 + lr + {0,8,16,24}
    int rr[4];
    #pragma unroll
    for (int i = 0; i < 4; i++) rr[i] = wrow * 32 + lr + i * 8;

    int idxNxt = ldIdx(0);
    fillA(0, idxNxt);
    fillB(0, 0);
    cp_commit();
    idxNxt = ldIdx(1);

    for (int kk = 0; kk < 27; kk++) {
        const int buf = kk & 1;
        if (kk + 1 < 27) {
            fillA(buf ^ 1, idxNxt);
            fillB(kk + 1, buf ^ 1);
            cp_commit();
            if (kk + 2 < 27) idxNxt = ldIdx(kk + 2);  // hidden under MMAs below
            cp_wait<1>();                 // stage kk landed (this thread)
        } else {
            cp_wait<0>();
        }
        __syncthreads();                  // stage kk visible CTA-wide

        const float* Ab = sm + buf * 8704;
        const float* Bb = sm + 17408 + buf * 4608;

        #pragma unroll
        for (int k8 = 0; k8 < 8; k8++) {
            uint32_t af[4][2];
            #pragma unroll
            for (int i = 0; i < 4; i++) {
                int r = rr[i];
                af[i][0] = __float_as_uint(Ab[r * 68 + k8 * 8 + la3]);
                af[i][1] = __float_as_uint(Ab[r * 68 + k8 * 8 + 4 + la3]);
            }
            uint32_t bf[4][2];
            #pragma unroll
            for (int nt = 0; nt < 4; nt++) {
                int n = wcol * 32 + nt * 8 + lr;
                bf[nt][0] = __float_as_uint(Bb[(k8 * 8 + la3)     * 72 + n]);
                bf[nt][1] = __float_as_uint(Bb[(k8 * 8 + 4 + la3) * 72 + n]);
            }
            #pragma unroll
            for (int mt = 0; mt < 2; mt++) {
                uint32_t a[4] = { af[2 * mt][0], af[2 * mt + 1][0],
                                  af[2 * mt][1], af[2 * mt + 1][1] };
                #pragma unroll
                for (int nt = 0; nt < 4; nt++)
                    mma_tf32(acc[mt][nt], a, bf[nt]);
            }
        }
        __syncthreads();                  // all warps done reading buf
    }

    // epilogue: bias + relu, register -> global
    #pragma unroll
    for (int nt = 0; nt < 4; nt++) {
        int cc = wcol * 32 + nt * 8 + 2 * la3;
        float rb0 = rb[cc], rb1 = rb[cc + 1];
        #pragma unroll
        for (int mt = 0; mt < 2; mt++) {
            int r0 = rowBase + wrow * 32 + mt * 16 + lr;
            float2 v0, v1;
            v0.x = fmaxf(acc[mt][nt][0] + rb0, 0.f);
            v0.y = fmaxf(acc[mt][nt][1] + rb1, 0.f);
            v1.x = fmaxf(acc[mt][nt][2] + rb0, 0.f);
            v1.y = fmaxf(acc[mt][nt][3] + rb1, 0.f);
            *(float2*)(outp + (size_t)r0 * 64 + cc)       = v0;
            *(float2*)(outp + (size_t)(r0 + 8) * 64 + cc) = v1;
        }
    }
}

// ---------------------------------------------------------------------------
// GEMM2: out = x + concat(r2 + 2*y[:,:64], y[:,64:]) @ w2 + b2   (unchanged)
// ---------------------------------------------------------------------------
__global__ __launch_bounds__(256) void gemm2_kernel(
    const float* __restrict__ x,
    const float* __restrict__ w2,
    const float* __restrict__ b2,
    float* __restrict__ out)
{
    extern __shared__ float smem[];
    float* As = smem;
    float* Bs = smem + 64 * 132;

    const int tid = threadIdx.x;
    const int rowBase = blockIdx.x * 64;

    #pragma unroll
    for (int i = 0; i < 16; i++) {
        int j = tid + i * 256;
        int row = j >> 5, seg = j & 31;
        cp16(smem_u32(Bs + row * 132 + seg * 4), w2 + j * 4, 16);
    }
    cp_commit();

    #pragma unroll
    for (int i = 0; i < 8; i++) {
        int j = tid + i * 256;
        int row = j >> 5, seg = j & 31;
        int n = rowBase + row;
        float4 v;
        if (seg < 16) {
            float4 r = *(const float4*)(g_r2 + (size_t)n * 64  + seg * 4);
            float4 y = *(const float4*)(g_y  + (size_t)n * 128 + seg * 4);
            v.x = fmaf(2.f, y.x, r.x);
            v.y = fmaf(2.f, y.y, r.y);
            v.z = fmaf(2.f, y.z, r.z);
            v.w = fmaf(2.f, y.w, r.w);
        } else {
            v = *(const float4*)(g_y + (size_t)n * 128 + seg * 4);
        }
        *(float4*)(As + row * 132 + seg * 4) = v;
    }
    cp_wait<0>();
    __syncthreads();

    const int warp = tid >> 5;
    const int mw = warp >> 1, nw = warp & 1;

    wmma::fragment<wmma::accumulator, 16, 16, 8, float> c[4];
    #pragma unroll
    for (int f = 0; f < 4; f++) wmma::fill_fragment(c[f], 0.f);

    #pragma unroll
    for (int kk = 0; kk < 16; kk++) {
        wmma::fragment<wmma::matrix_a, 16, 16, 8, wmma::precision::tf32, wmma::row_major> a;
        wmma::load_matrix_sync(a, As + (mw * 16) * 132 + kk * 8, 132);
        #pragma unroll
        for (int f = 0; f < 4; f++) {
            wmma::fragment<wmma::matrix_b, 16, 16, 8, wmma::precision::tf32, wmma::row_major> b;
            wmma::load_matrix_sync(b, Bs + (kk * 8) * 132 + nw * 64 + f * 16, 132);
            wmma::mma_sync(c[f], a, b, c[f]);
        }
    }
    __syncthreads();
    #pragma unroll
    for (int f = 0; f < 4; f++)
        wmma::store_matrix_sync(As + (mw * 16) * 132 + nw * 64 + f * 16, c[f], 132,
                                wmma::mem_row_major);
    __syncthreads();

    #pragma unroll
    for (int i = 0; i < 8; i++) {
        int j = tid + i * 256;
        int row = j >> 5, seg = j & 31;
        int n = rowBase + row;
        if (n < NP) {
            float4 v  = *(float4*)(As + row * 132 + seg * 4);
            float4 bb = *(const float4*)(b2 + seg * 4);
            float4 xr = *(const float4*)(x + (size_t)n * 128 + seg * 4);
            v.x += bb.x + xr.x;
            v.y += bb.y + xr.y;
            v.z += bb.z + xr.z;
            v.w += bb.w + xr.w;
            *(float4*)(out + (size_t)n * 128 + seg * 4) = v;
        }
    }
}

// ---------------------------------------------------------------------------
extern "C" void kernel_launch(void* const* d_in, const int* in_sizes, int n_in,
                              void* d_out, int out_size)
{
    const float* x   = (const float*)d_in[0];
    const float* w1  = (const float*)d_in[1];
    const float* b1  = (const float*)d_in[2];
    const float* w2  = (const float*)d_in[3];
    const float* b2  = (const float*)d_in[4];
    const float* rw1 = (const float*)d_in[5];
    const float* rb1 = (const float*)d_in[6];
    const float* rw2 = (const float*)d_in[7];
    const float* rb2 = (const float*)d_in[8];
    const int*   nbr = (const int*)  d_in[9];
    float* out = (float*)d_out;

    const int SMEM_G = (64 + 128) * 132 * (int)sizeof(float);             // ~99 KB
    const int SMEM_S = (2 * 128 * 68 + 2 * 64 * 72) * (int)sizeof(float); // 106496 B
    static bool attr_done = false;
    if (!attr_done) {
        cudaFuncSetAttribute(gemm1_kernel, cudaFuncAttributeMaxDynamicSharedMemorySize, SMEM_G);
        cudaFuncSetAttribute(gemm2_kernel, cudaFuncAttributeMaxDynamicSharedMemorySize, SMEM_G);
        cudaFuncSetAttribute(sconv_mma<0>, cudaFuncAttributeMaxDynamicSharedMemorySize, SMEM_S);
        cudaFuncSetAttribute(sconv_mma<1>, cudaFuncAttributeMaxDynamicSharedMemorySize, SMEM_S);
        attr_done = true;
    }

    const int gridG = NPAD / 64;    // 1564
    const int gridS = NPAD / 128;   // 782

    gemm1_kernel<<<gridG, 256, SMEM_G>>>(x, w1, b1);
    sconv_mma<0><<<gridS, 256, SMEM_S>>>(nbr, rw1, rb1);
    sconv_mma<1><<<gridS, 256, SMEM_S>>>(nbr, rw2, rb2);
    gemm2_kernel<<<gridG, 256, SMEM_G>>>(x, w2, b2, out);
}